// round 14
// baseline (speedup 1.0000x reference)
#include <cuda_runtime.h>
#include <math.h>

#define Bsz 4
#define C 64
#define H 128
#define W 128
#define N 16384   // H*W per batch
#define OC 89
#define YP2 36    // [c][p] tile pitch for 32 positions (mult of 4 -> 16B rows)

// scratch (__device__ globals; allocation is forbidden)
__device__ float g_lat_t[Bsz * N * C];    // latents channels-last [b][p][c]
__device__ float g_qf[Bsz * N * C];       // bilinear-sampled features [b][n][c]
__device__ float g_zyv[Bsz * N * 192];    // per row: zq[0:64] | yc[64:128] | vo[128:192]
// pre-duplicated folded weights: g_Wd[c2*128+j] = {w(2c2,j),w(2c2,j),w(2c2+1,j),w(2c2+1,j)}
__device__ ulonglong2 g_Wd[32 * 128];
__device__ float g_bias[128];             // GEMM bias: zq cols = w3, vo cols = 0
__device__ float g_bo[64];                // final output bias (beta_v@w_out + b_out)

// ---------------- f32x2 helpers (sm_103a packed fp32) ----------------------
__device__ __forceinline__ void ffma2(unsigned long long& d,
                                      unsigned long long a,
                                      unsigned long long b) {
    asm("fma.rn.f32x2 %0, %1, %2, %0;" : "+l"(d) : "l"(a), "l"(b));
}
__device__ __forceinline__ unsigned long long dup_f32(float v) {
    unsigned long long r;
    asm("mov.b64 %0, {%1, %1};" : "=l"(r) : "f"(v));
    return r;
}
__device__ __forceinline__ float2 ull_to_f2(unsigned long long v) {
    float2 r;
    asm("mov.b64 {%0, %1}, %2;" : "=f"(r.x), "=f"(r.y) : "l"(v));
    return r;
}

// ---------------------------------------------------------------------------
// K0: fused transpose + weight-prep.
// ---------------------------------------------------------------------------
__global__ void k_pre(const float* __restrict__ lat,
                      const float* __restrict__ w_q,
                      const float* __restrict__ w_kv,
                      const float* __restrict__ w_out,
                      const float* __restrict__ lnq_s,
                      const float* __restrict__ lnq_b,
                      const float* __restrict__ lnc_s,
                      const float* __restrict__ lnc_b,
                      const float* __restrict__ b_out) {
    __shared__ float s[64][65];
    int tid = threadIdx.x;
    if (blockIdx.x < 1024) {
        int b  = blockIdx.x >> 8;
        int pb = (blockIdx.x & 255) * 64;
        const float* src = lat + (size_t)b * N * C;
        {
            int pq = tid & 63, cg = tid >> 6;
            #pragma unroll
            for (int k = 0; k < 16; k++) {
                int c = cg * 16 + k;
                s[c][pq] = src[(size_t)c * N + pb + pq];
            }
        }
        __syncthreads();
        float* dst = g_lat_t + (size_t)b * N * C;
        {
            int cl = tid & 63, pg = tid >> 6;
            #pragma unroll
            for (int k = 0; k < 16; k++) {
                int p = pg * 16 + k;
                dst[(size_t)(pb + p) * C + cl] = s[cl][p];
            }
        }
        return;
    }

    // ---- prep path ----
    int j = blockIdx.x - 1024;
    if (tid >= 64) return;
    int t = tid;
    float* Wf = (float*)g_Wd;
    float* red = &s[0][0];

    if (j < 64) {
        float sum = 0.f;
        #pragma unroll 8
        for (int tt = 0; tt < 64; tt++)
            sum += w_q[t * 64 + tt] * w_kv[j * 128 + tt];
        float m = 0.125f * lnq_s[t] * lnc_s[j] * sum;
        int base = ((t >> 1) * 128 + j) * 4 + (t & 1) * 2;
        Wf[base] = m; Wf[base + 1] = m;

        float bq = 0.f;
        #pragma unroll 8
        for (int c = 0; c < 64; c++) bq += lnq_b[c] * w_q[c * 64 + t];
        red[t] = w_kv[j * 128 + t] * bq;
        __syncthreads();
        if (t < 32) {
            float v = red[t] + red[t + 32];
            #pragma unroll
            for (int o = 16; o > 0; o >>= 1) v += __shfl_xor_sync(~0u, v, o);
            if (t == 0) g_bias[j] = 0.125f * lnc_s[j] * v;
        }
    } else {
        int jj = j - 64;
        float sum = 0.f;
        #pragma unroll 8
        for (int tt = 0; tt < 64; tt++)
            sum += w_kv[t * 128 + 64 + tt] * w_out[tt * 64 + jj];
        float m = lnc_s[t] * sum;
        int base = ((t >> 1) * 128 + j) * 4 + (t & 1) * 2;
        Wf[base] = m; Wf[base + 1] = m;

        float bv = 0.f;
        #pragma unroll 8
        for (int c = 0; c < 64; c++) bv += lnc_b[c] * w_kv[c * 128 + 64 + t];
        red[t] = bv * w_out[t * 64 + jj];
        __syncthreads();
        if (t < 32) {
            float v = red[t] + red[t + 32];
            #pragma unroll
            for (int o = 16; o > 0; o >>= 1) v += __shfl_xor_sync(~0u, v, o);
            if (t == 0) {
                g_bo[jj] = v + b_out[jj];
                g_bias[j] = 0.f;
            }
        }
    }
}

// ---------------------------------------------------------------------------
// K1: bilinear sample of latents. One warp per point.
// ---------------------------------------------------------------------------
__global__ void k_sample_lat(const float* __restrict__ coords) {
    int gwarp = (blockIdx.x * blockDim.x + threadIdx.x) >> 5;
    int lane  = threadIdx.x & 31;
    if (gwarp >= Bsz * N) return;
    int b = gwarp >> 14;

    float y = coords[(size_t)gwarp * 2 + 0];   // xy = flip(coords)
    float x = coords[(size_t)gwarp * 2 + 1];
    float ix = ((x + 1.f) * (float)W - 1.f) * 0.5f;
    float iy = ((y + 1.f) * (float)H - 1.f) * 0.5f;
    float x0f = floorf(ix), y0f = floorf(iy);
    float wx1 = ix - x0f, wy1 = iy - y0f;
    int x0 = (int)x0f, y0 = (int)y0f;

    const float* base = g_lat_t + (size_t)b * N * C;
    float2 acc = make_float2(0.f, 0.f);
    #pragma unroll
    for (int dy = 0; dy < 2; dy++) {
        #pragma unroll
        for (int dx = 0; dx < 2; dx++) {
            int xc = x0 + dx, yc = y0 + dy;
            float wgt = (dx ? wx1 : 1.f - wx1) * (dy ? wy1 : 1.f - wy1);
            bool valid = (xc >= 0) && (xc < W) && (yc >= 0) && (yc < H);
            int xi = min(max(xc, 0), W - 1);
            int yi = min(max(yc, 0), H - 1);
            float wv = valid ? wgt : 0.f;
            float2 t = ((const float2*)(base + ((size_t)yi * W + xi) * C))[lane];
            acc.x += wv * t.x;
            acc.y += wv * t.y;
        }
    }
    ((float2*)(g_qf + (size_t)gwarp * C))[lane] = acc;
}

// ---------------------------------------------------------------------------
// K2: zq|vo GEMM + yc passthrough. Block = 128 thr (4 warps), 32 positions.
//   R13 tiling; epilogue: passthrough via float4 STG, deeper unroll.
// ---------------------------------------------------------------------------
__global__ void __launch_bounds__(128) k_zyv() {
    __shared__ float yq[64 * YP2];
    __shared__ float yc[64 * YP2];
    int b  = blockIdx.x >> 9;           // 512 blocks per batch
    int pb = (blockIdx.x & 511) * 32;
    int tid = threadIdx.x;

    // yq tile: global rows [p][c] -> smem [c][p], float4 reads
    const float4* qrow4 = (const float4*)(g_qf + ((size_t)b * N + pb) * 64);
    for (int idx = tid; idx < 512; idx += 128) {
        int p = idx >> 4, c4 = idx & 15;
        float4 v = qrow4[idx];
        yq[(c4 * 4 + 0) * YP2 + p] = v.x;
        yq[(c4 * 4 + 1) * YP2 + p] = v.y;
        yq[(c4 * 4 + 2) * YP2 + p] = v.z;
        yq[(c4 * 4 + 3) * YP2 + p] = v.w;
    }
    // yc tile: flat columns, already [c][p], float4 reads+writes
    const float* qb = g_qf + (size_t)b * N * 64;
    for (int idx = tid; idx < 512; idx += 128) {
        int c = idx >> 3, p4 = idx & 7;
        float4 v = *(const float4*)(qb + (size_t)c * N + pb + p4 * 4);
        *(float4*)&yc[c * YP2 + p4 * 4] = v;
    }
    __syncthreads();

    // LN (normalize only; all scales/biases folded into weights)
    if (tid < 64) {
        float* col = ((tid < 32) ? yq : yc) + (tid & 31);
        float s = 0.f, sq = 0.f;
        #pragma unroll 8
        for (int c = 0; c < 64; c++) { float v = col[c * YP2]; s += v; sq += v * v; }
        float mu = s * (1.f / 64.f);
        float var = sq * (1.f / 64.f) - mu * mu;
        float rstd = rsqrtf(var + 1e-5f);
        #pragma unroll 8
        for (int c = 0; c < 64; c++) col[c * YP2] = (col[c * YP2] - mu) * rstd;
    }
    __syncthreads();

    int warp = tid >> 5, lane = tid & 31;
    bool isQ = warp < 2;
    int p0 = (warp & 1) * 16;
    const float* yb = isQ ? yq : yc;
    int jA = (isQ ? 0 : 64) + lane;     // GEMM col
    int jB = jA + 32;

    unsigned long long accA[8], accB[8];
    {
        unsigned long long bA = dup_f32(g_bias[jA]);
        unsigned long long bB = dup_f32(g_bias[jB]);
        #pragma unroll
        for (int i = 0; i < 8; i++) { accA[i] = bA; accB[i] = bB; }
    }

    #pragma unroll 8
    for (int c2 = 0; c2 < 32; c2++) {
        ulonglong2 wA = g_Wd[c2 * 128 + jA];   // .x = dup w(2c2,jA), .y = dup w(2c2+1,jA)
        ulonglong2 wB = g_Wd[c2 * 128 + jB];
        const ulonglong2* y0 = (const ulonglong2*)&yb[(2 * c2) * YP2 + p0];
        const ulonglong2* y1 = (const ulonglong2*)&yb[(2 * c2 + 1) * YP2 + p0];
        #pragma unroll
        for (int m = 0; m < 4; m++) {
            ulonglong2 u = y0[m];
            ffma2(accA[2 * m],     u.x, wA.x);
            ffma2(accA[2 * m + 1], u.y, wA.x);
            ffma2(accB[2 * m],     u.x, wB.x);
            ffma2(accB[2 * m + 1], u.y, wB.x);
        }
        #pragma unroll
        for (int m = 0; m < 4; m++) {
            ulonglong2 u = y1[m];
            ffma2(accA[2 * m],     u.x, wA.y);
            ffma2(accA[2 * m + 1], u.y, wA.y);
            ffma2(accB[2 * m],     u.x, wB.y);
            ffma2(accB[2 * m + 1], u.y, wB.y);
        }
    }

    // store: zq -> [0:64], vo -> [128:192]
    int sA = isQ ? jA : jA + 64;
    int sB = sA + 32;
    float* ob = g_zyv + ((size_t)b * N + pb + p0) * 192;
    #pragma unroll
    for (int i = 0; i < 8; i++) {
        float2 a = ull_to_f2(accA[i]);
        float2 bv = ull_to_f2(accB[i]);
        ob[(size_t)(2 * i) * 192 + sA]     = a.x;
        ob[(size_t)(2 * i + 1) * 192 + sA] = a.y;
        ob[(size_t)(2 * i) * 192 + sB]     = bv.x;
        ob[(size_t)(2 * i + 1) * 192 + sB] = bv.y;
    }

    // yc passthrough -> [64:128] via float4 stores (gather 4 strided smem reads)
    #pragma unroll
    for (int k = 0; k < 4; k++) {
        int idx = tid + k * 128;        // 0..511
        int p  = idx & 31;
        int c4 = idx >> 5;              // 0..15
        float4 v;
        v.x = yc[(c4 * 4 + 0) * YP2 + p];
        v.y = yc[(c4 * 4 + 1) * YP2 + p];
        v.z = yc[(c4 * 4 + 2) * YP2 + p];
        v.w = yc[(c4 * 4 + 3) * YP2 + p];
        *(float4*)&g_zyv[((size_t)b * N + pb + p) * 192 + 64 + c4 * 4] = v;
    }
}

// ---------------------------------------------------------------------------
// K3: attention (2D-tiled, smem halo) + fused tail — R10/R13 configuration
//   (group-local sim, warp-wide V with shfl broadcast; measured 36.5-36.9us).
// ---------------------------------------------------------------------------
__global__ void __launch_bounds__(256) k_attn(const float* __restrict__ coords,
                                              const float* __restrict__ image,
                                              float* __restrict__ out) {
    __shared__ float kv[60 * 128];   // 30720 B: per halo row: yc[0:64] | vo[64:128]
    int tile = blockIdx.x;           // 2048
    int b = tile >> 9;
    int t = tile & 511;
    int th = t >> 4;
    int tw = t & 15;
    int h0 = th * 4, w0 = tw * 8;
    int tid = threadIdx.x;

    const float* kvb = g_zyv + (size_t)b * N * 192;
    for (int i = tid; i < 1920; i += 256) {
        int r = i >> 5, q4 = i & 31;
        int ri = r / 10, rj = r % 10;
        int gh = min(max(h0 - 1 + ri, 0), H - 1);
        int gw = min(max(w0 - 1 + rj, 0), W - 1);
        ((float4*)kv)[r * 32 + q4] =
            *(const float4*)(kvb + (size_t)(gh * W + gw) * 192 + 64 + q4 * 4);
    }
    __syncthreads();

    int warp = tid >> 5, lane = tid & 31;
    int g8 = lane >> 3;          // query group within warp (0..3)
    int l8 = lane & 7;           // lane within group

    // my group's query
    int qidx = warp * 4 + g8;    // 0..31 within tile
    int qh = h0 + (qidx >> 3), qw = w0 + (qidx & 7);
    int gq = b * N + qh * W + qw;

    // zq channels owned by this lane: [l8*8, l8*8+8)
    const float* zrow = g_zyv + (size_t)gq * 192 + l8 * 8;
    float4 qa = *(const float4*)(zrow);
    float4 qb4 = *(const float4*)(zrow + 4);

    // 9 neighbor rows + grouped dot products
    int rr[9];
    float att[9];
    #pragma unroll
    for (int k = 0; k < 9; k++) {
        int di = k / 3 - 1, dj = k % 3 - 1;
        int nh = min(max(qh + di, 0), H - 1) - h0 + 1;
        int nw = min(max(qw + dj, 0), W - 1) - w0 + 1;
        rr[k] = nh * 10 + nw;
        const float* kr = kv + rr[k] * 128 + l8 * 8;
        float4 ka = *(const float4*)(kr);
        float4 kb = *(const float4*)(kr + 4);
        float part = qa.x * ka.x + qa.y * ka.y + qa.z * ka.z + qa.w * ka.w
                   + qb4.x * kb.x + qb4.y * kb.y + qb4.z * kb.z + qb4.w * kb.w;
        part += __shfl_xor_sync(~0u, part, 1);
        part += __shfl_xor_sync(~0u, part, 2);
        part += __shfl_xor_sync(~0u, part, 4);
        att[k] = part;
    }
    // softmax (redundant within group)
    float m = att[0];
    #pragma unroll
    for (int k = 1; k < 9; k++) m = fmaxf(m, att[k]);
    float den = 0.f;
    #pragma unroll
    for (int k = 0; k < 9; k++) { att[k] = __expf(att[k] - m); den += att[k]; }
    float inv = 1.f / den;

    // V phase: warp-wide per query, coalesced loads/stores
    float bo0 = g_bo[lane], bo1 = g_bo[lane + 32];
    #pragma unroll
    for (int q = 0; q < 4; q++) {
        int src = q * 8;
        float o0 = 0.f, o1 = 0.f;
        #pragma unroll
        for (int k = 0; k < 9; k++) {
            float a = __shfl_sync(~0u, att[k], src);
            int r   = __shfl_sync(~0u, rr[k],  src);
            const float* vr = kv + r * 128 + 64;
            o0 += a * vr[lane];
            o1 += a * vr[32 + lane];
        }
        float ai = __shfl_sync(~0u, inv, src);
        int qi2 = warp * 4 + q;
        int g2 = b * N + (h0 + (qi2 >> 3)) * W + (w0 + (qi2 & 7));
        out[(size_t)g2 * OC + lane]      = o0 * ai + bo0;
        out[(size_t)g2 * OC + 32 + lane] = o1 * ai + bo1;
    }

    // ---- fused tail: threads 0-31, one query each ----
    if (tid < 32) {
        int tqi = tid >> 3, tqj = tid & 7;
        int g = b * N + (h0 + tqi) * W + (w0 + tqj);
        float y = coords[(size_t)g * 2 + 0];
        float x = coords[(size_t)g * 2 + 1];

        float ix = ((x + 1.f) * 256.f - 1.f) * 0.5f;
        float iy = ((y + 1.f) * 256.f - 1.f) * 0.5f;
        float x0f = floorf(ix), y0f = floorf(iy);
        float wx = ix - x0f, wy = iy - y0f;
        int x0 = (int)x0f, y0 = (int)y0f;
        const float* img = image + (size_t)b * 256 * 256;

        float ix2 = ((x + 1.f) * 128.f - 1.f) * 0.5f;
        float iy2 = ((y + 1.f) * 128.f - 1.f) * 0.5f;
        float x0f2 = floorf(ix2), y0f2 = floorf(iy2);
        float wx2 = ix2 - x0f2, wy2 = iy2 - y0f2;
        int x02 = (int)x0f2, y02 = (int)y0f2;

        float qin = 0.f, qcy = 0.f, qcx = 0.f;
        #pragma unroll
        for (int dy = 0; dy < 2; dy++) {
            #pragma unroll
            for (int dx = 0; dx < 2; dx++) {
                {
                    int xc = x0 + dx, yc2 = y0 + dy;
                    float wgt = (dx ? wx : 1.f - wx) * (dy ? wy : 1.f - wy);
                    bool valid = (xc >= 0) && (xc < 256) && (yc2 >= 0) && (yc2 < 256);
                    int xi = min(max(xc, 0), 255), yi = min(max(yc2, 0), 255);
                    qin += (valid ? wgt : 0.f) * img[yi * 256 + xi];
                }
                {
                    int xc = x02 + dx, yc2 = y02 + dy;
                    float wgt = (dx ? wx2 : 1.f - wx2) * (dy ? wy2 : 1.f - wy2);
                    bool valid = (xc >= 0) && (xc < 128) && (yc2 >= 0) && (yc2 < 128);
                    int xi = min(max(xc, 0), 127), yi = min(max(yc2, 0), 127);
                    float wv = valid ? wgt : 0.f;
                    qcy += wv * (-1.f + (2.f * yi + 1.f) * (1.f / 128.f));
                    qcx += wv * (-1.f + (2.f * xi + 1.f) * (1.f / 128.f));
                }
            }
        }

        float* o = out + (size_t)g * OC + 64;
        o[0] = qin;
        float cy = (qcy + 1.f) * 0.5f;
        float cx = (qcx + 1.f) * 0.5f;
        const float PI = 3.14159265358979323846f;
        #pragma unroll
        for (int k = 0; k < 6; k++) {
            float f = (float)(1 << k) * PI;
            float sy, cvy, sx, cvx;
            sincosf(cy * f, &sy, &cvy);
            sincosf(cx * f, &sx, &cvx);
            o[1 + k]          = sy;
            o[1 + 6 + k]      = sx;
            o[1 + 12 + k]     = cvy;
            o[1 + 12 + 6 + k] = cvx;
        }
    }
}

extern "C" void kernel_launch(void* const* d_in, const int* in_sizes, int n_in,
                              void* d_out, int out_size) {
    const float* image   = (const float*)d_in[0];
    const float* latents = (const float*)d_in[1];
    const float* coords  = (const float*)d_in[2];
    const float* lnq_s   = (const float*)d_in[3];
    const float* lnq_b   = (const float*)d_in[4];
    const float* lnc_s   = (const float*)d_in[5];
    const float* lnc_b   = (const float*)d_in[6];
    const float* w_q     = (const float*)d_in[7];
    const float* w_kv    = (const float*)d_in[8];
    const float* w_out   = (const float*)d_in[9];
    const float* b_out   = (const float*)d_in[10];
    float* out = (float*)d_out;

    k_pre       <<<1152, 256>>>(latents, w_q, w_kv, w_out,
                                lnq_s, lnq_b, lnc_s, lnc_b, b_out);
    k_sample_lat<<<8192, 256>>>(coords);
    k_zyv       <<<2048, 128>>>();
    k_attn      <<<2048, 256>>>(coords, image, out);
}

// round 15
// speedup vs baseline: 1.0691x; 1.0691x over previous
#include <cuda_runtime.h>
#include <math.h>

#define Bsz 4
#define C 64
#define H 128
#define W 128
#define N 16384   // H*W per batch
#define OC 89
#define YP2 36    // [c][p] tile pitch for 32 positions (mult of 4 -> 16B rows)

// scratch (__device__ globals; allocation is forbidden)
__device__ float g_lat_t[Bsz * N * C];    // latents channels-last [b][p][c]
__device__ float g_qf[Bsz * N * C];       // bilinear-sampled features [b][n][c]
__device__ float g_zyv[Bsz * N * 192];    // per row: zq[0:64] | yc[64:128] | vo[128:192]
// pre-duplicated folded weights: g_Wd[c2*128+j] = {w(2c2,j),w(2c2,j),w(2c2+1,j),w(2c2+1,j)}
__device__ ulonglong2 g_Wd[32 * 128];
__device__ float g_bias[128];             // GEMM bias: zq cols = w3, vo cols = 0
__device__ float g_bo[64];                // final output bias (beta_v@w_out + b_out)

// ---------------- f32x2 helpers (sm_103a packed fp32) ----------------------
__device__ __forceinline__ void ffma2(unsigned long long& d,
                                      unsigned long long a,
                                      unsigned long long b) {
    asm("fma.rn.f32x2 %0, %1, %2, %0;" : "+l"(d) : "l"(a), "l"(b));
}
__device__ __forceinline__ unsigned long long dup_f32(float v) {
    unsigned long long r;
    asm("mov.b64 %0, {%1, %1};" : "=l"(r) : "f"(v));
    return r;
}
__device__ __forceinline__ float2 ull_to_f2(unsigned long long v) {
    float2 r;
    asm("mov.b64 {%0, %1}, %2;" : "=f"(r.x), "=f"(r.y) : "l"(v));
    return r;
}

// ---------------------------------------------------------------------------
// K0: fused transpose + weight-prep.
// ---------------------------------------------------------------------------
__global__ void k_pre(const float* __restrict__ lat,
                      const float* __restrict__ w_q,
                      const float* __restrict__ w_kv,
                      const float* __restrict__ w_out,
                      const float* __restrict__ lnq_s,
                      const float* __restrict__ lnq_b,
                      const float* __restrict__ lnc_s,
                      const float* __restrict__ lnc_b,
                      const float* __restrict__ b_out) {
    __shared__ float s[64][65];
    int tid = threadIdx.x;
    if (blockIdx.x < 1024) {
        int b  = blockIdx.x >> 8;
        int pb = (blockIdx.x & 255) * 64;
        const float* src = lat + (size_t)b * N * C;
        {
            int pq = tid & 63, cg = tid >> 6;
            #pragma unroll
            for (int k = 0; k < 16; k++) {
                int c = cg * 16 + k;
                s[c][pq] = src[(size_t)c * N + pb + pq];
            }
        }
        __syncthreads();
        float* dst = g_lat_t + (size_t)b * N * C;
        {
            int cl = tid & 63, pg = tid >> 6;
            #pragma unroll
            for (int k = 0; k < 16; k++) {
                int p = pg * 16 + k;
                dst[(size_t)(pb + p) * C + cl] = s[cl][p];
            }
        }
        return;
    }

    // ---- prep path ----
    int j = blockIdx.x - 1024;
    if (tid >= 64) return;
    int t = tid;
    float* Wf = (float*)g_Wd;
    float* red = &s[0][0];

    if (j < 64) {
        float sum = 0.f;
        #pragma unroll 8
        for (int tt = 0; tt < 64; tt++)
            sum += w_q[t * 64 + tt] * w_kv[j * 128 + tt];
        float m = 0.125f * lnq_s[t] * lnc_s[j] * sum;
        int base = ((t >> 1) * 128 + j) * 4 + (t & 1) * 2;
        Wf[base] = m; Wf[base + 1] = m;

        float bq = 0.f;
        #pragma unroll 8
        for (int c = 0; c < 64; c++) bq += lnq_b[c] * w_q[c * 64 + t];
        red[t] = w_kv[j * 128 + t] * bq;
        __syncthreads();
        if (t < 32) {
            float v = red[t] + red[t + 32];
            #pragma unroll
            for (int o = 16; o > 0; o >>= 1) v += __shfl_xor_sync(~0u, v, o);
            if (t == 0) g_bias[j] = 0.125f * lnc_s[j] * v;
        }
    } else {
        int jj = j - 64;
        float sum = 0.f;
        #pragma unroll 8
        for (int tt = 0; tt < 64; tt++)
            sum += w_kv[t * 128 + 64 + tt] * w_out[tt * 64 + jj];
        float m = lnc_s[t] * sum;
        int base = ((t >> 1) * 128 + j) * 4 + (t & 1) * 2;
        Wf[base] = m; Wf[base + 1] = m;

        float bv = 0.f;
        #pragma unroll 8
        for (int c = 0; c < 64; c++) bv += lnc_b[c] * w_kv[c * 128 + 64 + t];
        red[t] = bv * w_out[t * 64 + jj];
        __syncthreads();
        if (t < 32) {
            float v = red[t] + red[t + 32];
            #pragma unroll
            for (int o = 16; o > 0; o >>= 1) v += __shfl_xor_sync(~0u, v, o);
            if (t == 0) {
                g_bo[jj] = v + b_out[jj];
                g_bias[j] = 0.f;
            }
        }
    }
}

// ---------------------------------------------------------------------------
// K1: bilinear sample of latents. HALF-warp per point (2 points per warp):
//   lanes 0-15 point A, lanes 16-31 point B; lane owns 4 channels (float4).
// ---------------------------------------------------------------------------
__global__ void k_sample_lat(const float* __restrict__ coords) {
    int warp_g = (blockIdx.x * blockDim.x + threadIdx.x) >> 5;
    int lane = threadIdx.x & 31;
    int g = warp_g * 2 + (lane >> 4);
    if (g >= Bsz * N) return;
    int b = g >> 14;
    int l16 = lane & 15;

    float y = coords[(size_t)g * 2 + 0];   // xy = flip(coords)
    float x = coords[(size_t)g * 2 + 1];
    float ix = ((x + 1.f) * (float)W - 1.f) * 0.5f;
    float iy = ((y + 1.f) * (float)H - 1.f) * 0.5f;
    float x0f = floorf(ix), y0f = floorf(iy);
    float wx1 = ix - x0f, wy1 = iy - y0f;
    int x0 = (int)x0f, y0 = (int)y0f;

    const float* base = g_lat_t + (size_t)b * N * C;
    float4 acc = make_float4(0.f, 0.f, 0.f, 0.f);
    #pragma unroll
    for (int dy = 0; dy < 2; dy++) {
        #pragma unroll
        for (int dx = 0; dx < 2; dx++) {
            int xc = x0 + dx, yc = y0 + dy;
            float wgt = (dx ? wx1 : 1.f - wx1) * (dy ? wy1 : 1.f - wy1);
            bool valid = (xc >= 0) && (xc < W) && (yc >= 0) && (yc < H);
            int xi = min(max(xc, 0), W - 1);
            int yi = min(max(yc, 0), H - 1);
            float wv = valid ? wgt : 0.f;
            float4 t = ((const float4*)(base + ((size_t)yi * W + xi) * C))[l16];
            acc.x += wv * t.x;
            acc.y += wv * t.y;
            acc.z += wv * t.z;
            acc.w += wv * t.w;
        }
    }
    ((float4*)(g_qf + (size_t)g * C))[l16] = acc;
}

// ---------------------------------------------------------------------------
// K2: zq|vo GEMM + yc passthrough. Block = 128 thr (4 warps), 32 positions.
//   EXACT R13 configuration (best measured).
// ---------------------------------------------------------------------------
__global__ void __launch_bounds__(128) k_zyv() {
    __shared__ float yq[64 * YP2];
    __shared__ float yc[64 * YP2];
    int b  = blockIdx.x >> 9;           // 512 blocks per batch
    int pb = (blockIdx.x & 511) * 32;
    int tid = threadIdx.x;

    // yq tile: global rows [p][c] -> smem [c][p], float4 reads
    const float4* qrow4 = (const float4*)(g_qf + ((size_t)b * N + pb) * 64);
    for (int idx = tid; idx < 512; idx += 128) {
        int p = idx >> 4, c4 = idx & 15;
        float4 v = qrow4[idx];
        yq[(c4 * 4 + 0) * YP2 + p] = v.x;
        yq[(c4 * 4 + 1) * YP2 + p] = v.y;
        yq[(c4 * 4 + 2) * YP2 + p] = v.z;
        yq[(c4 * 4 + 3) * YP2 + p] = v.w;
    }
    // yc tile: flat columns, already [c][p], float4 reads+writes
    const float* qb = g_qf + (size_t)b * N * 64;
    for (int idx = tid; idx < 512; idx += 128) {
        int c = idx >> 3, p4 = idx & 7;
        float4 v = *(const float4*)(qb + (size_t)c * N + pb + p4 * 4);
        *(float4*)&yc[c * YP2 + p4 * 4] = v;
    }
    __syncthreads();

    // LN (normalize only; all scales/biases folded into weights)
    if (tid < 64) {
        float* col = ((tid < 32) ? yq : yc) + (tid & 31);
        float s = 0.f, sq = 0.f;
        #pragma unroll 8
        for (int c = 0; c < 64; c++) { float v = col[c * YP2]; s += v; sq += v * v; }
        float mu = s * (1.f / 64.f);
        float var = sq * (1.f / 64.f) - mu * mu;
        float rstd = rsqrtf(var + 1e-5f);
        #pragma unroll 8
        for (int c = 0; c < 64; c++) col[c * YP2] = (col[c * YP2] - mu) * rstd;
    }
    __syncthreads();

    int warp = tid >> 5, lane = tid & 31;
    bool isQ = warp < 2;
    int p0 = (warp & 1) * 16;
    const float* yb = isQ ? yq : yc;
    int jA = (isQ ? 0 : 64) + lane;     // GEMM col
    int jB = jA + 32;

    unsigned long long accA[8], accB[8];
    {
        unsigned long long bA = dup_f32(g_bias[jA]);
        unsigned long long bB = dup_f32(g_bias[jB]);
        #pragma unroll
        for (int i = 0; i < 8; i++) { accA[i] = bA; accB[i] = bB; }
    }

    #pragma unroll 4
    for (int c2 = 0; c2 < 32; c2++) {
        ulonglong2 wA = g_Wd[c2 * 128 + jA];   // .x = dup w(2c2,jA), .y = dup w(2c2+1,jA)
        ulonglong2 wB = g_Wd[c2 * 128 + jB];
        const ulonglong2* y0 = (const ulonglong2*)&yb[(2 * c2) * YP2 + p0];
        const ulonglong2* y1 = (const ulonglong2*)&yb[(2 * c2 + 1) * YP2 + p0];
        #pragma unroll
        for (int m = 0; m < 4; m++) {
            ulonglong2 u = y0[m];
            ffma2(accA[2 * m],     u.x, wA.x);
            ffma2(accA[2 * m + 1], u.y, wA.x);
            ffma2(accB[2 * m],     u.x, wB.x);
            ffma2(accB[2 * m + 1], u.y, wB.x);
        }
        #pragma unroll
        for (int m = 0; m < 4; m++) {
            ulonglong2 u = y1[m];
            ffma2(accA[2 * m],     u.x, wA.y);
            ffma2(accA[2 * m + 1], u.y, wA.y);
            ffma2(accB[2 * m],     u.x, wB.y);
            ffma2(accB[2 * m + 1], u.y, wB.y);
        }
    }

    // store: zq -> [0:64], vo -> [128:192]
    int sA = isQ ? jA : jA + 64;
    int sB = sA + 32;
    float* ob = g_zyv + ((size_t)b * N + pb + p0) * 192;
    #pragma unroll
    for (int i = 0; i < 8; i++) {
        float2 a = ull_to_f2(accA[i]);
        float2 bv = ull_to_f2(accB[i]);
        ob[(size_t)(2 * i) * 192 + sA]     = a.x;
        ob[(size_t)(2 * i + 1) * 192 + sA] = a.y;
        ob[(size_t)(2 * i) * 192 + sB]     = bv.x;
        ob[(size_t)(2 * i + 1) * 192 + sB] = bv.y;
    }

    // yc passthrough -> [64:128] (smem unchanged since LN sync)
    for (int idx = tid; idx < 2048; idx += 128) {
        int p = idx >> 6, c = idx & 63;
        g_zyv[((size_t)b * N + pb + p) * 192 + 64 + c] = yc[c * YP2 + p];
    }
}

// ---------------------------------------------------------------------------
// K3: attention (2D-tiled, smem halo) + fused tail — R10/R13 configuration
//   (group-local sim, warp-wide V with shfl broadcast; measured 36.5-36.9us).
// ---------------------------------------------------------------------------
__global__ void __launch_bounds__(256) k_attn(const float* __restrict__ coords,
                                              const float* __restrict__ image,
                                              float* __restrict__ out) {
    __shared__ float kv[60 * 128];   // 30720 B: per halo row: yc[0:64] | vo[64:128]
    int tile = blockIdx.x;           // 2048
    int b = tile >> 9;
    int t = tile & 511;
    int th = t >> 4;
    int tw = t & 15;
    int h0 = th * 4, w0 = tw * 8;
    int tid = threadIdx.x;

    const float* kvb = g_zyv + (size_t)b * N * 192;
    for (int i = tid; i < 1920; i += 256) {
        int r = i >> 5, q4 = i & 31;
        int ri = r / 10, rj = r % 10;
        int gh = min(max(h0 - 1 + ri, 0), H - 1);
        int gw = min(max(w0 - 1 + rj, 0), W - 1);
        ((float4*)kv)[r * 32 + q4] =
            *(const float4*)(kvb + (size_t)(gh * W + gw) * 192 + 64 + q4 * 4);
    }
    __syncthreads();

    int warp = tid >> 5, lane = tid & 31;
    int g8 = lane >> 3;          // query group within warp (0..3)
    int l8 = lane & 7;           // lane within group

    // my group's query
    int qidx = warp * 4 + g8;    // 0..31 within tile
    int qh = h0 + (qidx >> 3), qw = w0 + (qidx & 7);
    int gq = b * N + qh * W + qw;

    // zq channels owned by this lane: [l8*8, l8*8+8)
    const float* zrow = g_zyv + (size_t)gq * 192 + l8 * 8;
    float4 qa = *(const float4*)(zrow);
    float4 qb4 = *(const float4*)(zrow + 4);

    // 9 neighbor rows + grouped dot products
    int rr[9];
    float att[9];
    #pragma unroll
    for (int k = 0; k < 9; k++) {
        int di = k / 3 - 1, dj = k % 3 - 1;
        int nh = min(max(qh + di, 0), H - 1) - h0 + 1;
        int nw = min(max(qw + dj, 0), W - 1) - w0 + 1;
        rr[k] = nh * 10 + nw;
        const float* kr = kv + rr[k] * 128 + l8 * 8;
        float4 ka = *(const float4*)(kr);
        float4 kb = *(const float4*)(kr + 4);
        float part = qa.x * ka.x + qa.y * ka.y + qa.z * ka.z + qa.w * ka.w
                   + qb4.x * kb.x + qb4.y * kb.y + qb4.z * kb.z + qb4.w * kb.w;
        part += __shfl_xor_sync(~0u, part, 1);
        part += __shfl_xor_sync(~0u, part, 2);
        part += __shfl_xor_sync(~0u, part, 4);
        att[k] = part;
    }
    // softmax (redundant within group)
    float m = att[0];
    #pragma unroll
    for (int k = 1; k < 9; k++) m = fmaxf(m, att[k]);
    float den = 0.f;
    #pragma unroll
    for (int k = 0; k < 9; k++) { att[k] = __expf(att[k] - m); den += att[k]; }
    float inv = 1.f / den;

    // V phase: warp-wide per query, coalesced loads/stores
    float bo0 = g_bo[lane], bo1 = g_bo[lane + 32];
    #pragma unroll
    for (int q = 0; q < 4; q++) {
        int src = q * 8;
        float o0 = 0.f, o1 = 0.f;
        #pragma unroll
        for (int k = 0; k < 9; k++) {
            float a = __shfl_sync(~0u, att[k], src);
            int r   = __shfl_sync(~0u, rr[k],  src);
            const float* vr = kv + r * 128 + 64;
            o0 += a * vr[lane];
            o1 += a * vr[32 + lane];
        }
        float ai = __shfl_sync(~0u, inv, src);
        int qi2 = warp * 4 + q;
        int g2 = b * N + (h0 + (qi2 >> 3)) * W + (w0 + (qi2 & 7));
        out[(size_t)g2 * OC + lane]      = o0 * ai + bo0;
        out[(size_t)g2 * OC + 32 + lane] = o1 * ai + bo1;
    }

    // ---- fused tail: threads 0-31, one query each ----
    if (tid < 32) {
        int tqi = tid >> 3, tqj = tid & 7;
        int g = b * N + (h0 + tqi) * W + (w0 + tqj);
        float y = coords[(size_t)g * 2 + 0];
        float x = coords[(size_t)g * 2 + 1];

        float ix = ((x + 1.f) * 256.f - 1.f) * 0.5f;
        float iy = ((y + 1.f) * 256.f - 1.f) * 0.5f;
        float x0f = floorf(ix), y0f = floorf(iy);
        float wx = ix - x0f, wy = iy - y0f;
        int x0 = (int)x0f, y0 = (int)y0f;
        const float* img = image + (size_t)b * 256 * 256;

        float ix2 = ((x + 1.f) * 128.f - 1.f) * 0.5f;
        float iy2 = ((y + 1.f) * 128.f - 1.f) * 0.5f;
        float x0f2 = floorf(ix2), y0f2 = floorf(iy2);
        float wx2 = ix2 - x0f2, wy2 = iy2 - y0f2;
        int x02 = (int)x0f2, y02 = (int)y0f2;

        float qin = 0.f, qcy = 0.f, qcx = 0.f;
        #pragma unroll
        for (int dy = 0; dy < 2; dy++) {
            #pragma unroll
            for (int dx = 0; dx < 2; dx++) {
                {
                    int xc = x0 + dx, yc2 = y0 + dy;
                    float wgt = (dx ? wx : 1.f - wx) * (dy ? wy : 1.f - wy);
                    bool valid = (xc >= 0) && (xc < 256) && (yc2 >= 0) && (yc2 < 256);
                    int xi = min(max(xc, 0), 255), yi = min(max(yc2, 0), 255);
                    qin += (valid ? wgt : 0.f) * img[yi * 256 + xi];
                }
                {
                    int xc = x02 + dx, yc2 = y02 + dy;
                    float wgt = (dx ? wx2 : 1.f - wx2) * (dy ? wy2 : 1.f - wy2);
                    bool valid = (xc >= 0) && (xc < 128) && (yc2 >= 0) && (yc2 < 128);
                    int xi = min(max(xc, 0), 127), yi = min(max(yc2, 0), 127);
                    float wv = valid ? wgt : 0.f;
                    qcy += wv * (-1.f + (2.f * yi + 1.f) * (1.f / 128.f));
                    qcx += wv * (-1.f + (2.f * xi + 1.f) * (1.f / 128.f));
                }
            }
        }

        float* o = out + (size_t)g * OC + 64;
        o[0] = qin;
        float cy = (qcy + 1.f) * 0.5f;
        float cx = (qcx + 1.f) * 0.5f;
        const float PI = 3.14159265358979323846f;
        #pragma unroll
        for (int k = 0; k < 6; k++) {
            float f = (float)(1 << k) * PI;
            float sy, cvy, sx, cvx;
            sincosf(cy * f, &sy, &cvy);
            sincosf(cx * f, &sx, &cvx);
            o[1 + k]          = sy;
            o[1 + 6 + k]      = sx;
            o[1 + 12 + k]     = cvy;
            o[1 + 12 + 6 + k] = cvx;
        }
    }
}

extern "C" void kernel_launch(void* const* d_in, const int* in_sizes, int n_in,
                              void* d_out, int out_size) {
    const float* image   = (const float*)d_in[0];
    const float* latents = (const float*)d_in[1];
    const float* coords  = (const float*)d_in[2];
    const float* lnq_s   = (const float*)d_in[3];
    const float* lnq_b   = (const float*)d_in[4];
    const float* lnc_s   = (const float*)d_in[5];
    const float* lnc_b   = (const float*)d_in[6];
    const float* w_q     = (const float*)d_in[7];
    const float* w_kv    = (const float*)d_in[8];
    const float* w_out   = (const float*)d_in[9];
    const float* b_out   = (const float*)d_in[10];
    float* out = (float*)d_out;

    k_pre       <<<1152, 256>>>(latents, w_q, w_kv, w_out,
                                lnq_s, lnq_b, lnc_s, lnc_b, b_out);
    k_sample_lat<<<4096, 256>>>(coords);
    k_zyv       <<<2048, 128>>>();
    k_attn      <<<2048, 256>>>(coords, image, out);
}

// round 16
// speedup vs baseline: 1.0929x; 1.0222x over previous
#include <cuda_runtime.h>
#include <math.h>

#define Bsz 4
#define C 64
#define H 128
#define W 128
#define N 16384   // H*W per batch
#define OC 89
#define YP2 36    // [c][p] tile pitch for 32 positions (mult of 4 -> 16B rows)

// scratch (__device__ globals; allocation is forbidden)
__device__ float g_lat_t[Bsz * N * C];    // latents channels-last [b][p][c]
__device__ float g_qf[Bsz * N * C];       // bilinear-sampled features [b][n][c]
__device__ float g_zyv[Bsz * N * 192];    // per row: zq[0:64] | yc[64:128] | vo[128:192]
// pre-duplicated folded weights: g_Wd[c2*128+j] = {w(2c2,j),w(2c2,j),w(2c2+1,j),w(2c2+1,j)}
__device__ ulonglong2 g_Wd[32 * 128];
__device__ float g_bias[128];             // GEMM bias: zq cols = w3, vo cols = 0
__device__ float g_bo[64];                // final output bias (beta_v@w_out + b_out)

// ---------------- f32x2 helpers (sm_103a packed fp32) ----------------------
__device__ __forceinline__ void ffma2(unsigned long long& d,
                                      unsigned long long a,
                                      unsigned long long b) {
    asm("fma.rn.f32x2 %0, %1, %2, %0;" : "+l"(d) : "l"(a), "l"(b));
}
__device__ __forceinline__ unsigned long long dup_f32(float v) {
    unsigned long long r;
    asm("mov.b64 %0, {%1, %1};" : "=l"(r) : "f"(v));
    return r;
}
__device__ __forceinline__ float2 ull_to_f2(unsigned long long v) {
    float2 r;
    asm("mov.b64 {%0, %1}, %2;" : "=f"(r.x), "=f"(r.y) : "l"(v));
    return r;
}

// ---------------------------------------------------------------------------
// K0: fused transpose + weight-prep.
// ---------------------------------------------------------------------------
__global__ void k_pre(const float* __restrict__ lat,
                      const float* __restrict__ w_q,
                      const float* __restrict__ w_kv,
                      const float* __restrict__ w_out,
                      const float* __restrict__ lnq_s,
                      const float* __restrict__ lnq_b,
                      const float* __restrict__ lnc_s,
                      const float* __restrict__ lnc_b,
                      const float* __restrict__ b_out) {
    __shared__ float s[64][65];
    int tid = threadIdx.x;
    if (blockIdx.x < 1024) {
        int b  = blockIdx.x >> 8;
        int pb = (blockIdx.x & 255) * 64;
        const float* src = lat + (size_t)b * N * C;
        {
            int pq = tid & 63, cg = tid >> 6;
            #pragma unroll
            for (int k = 0; k < 16; k++) {
                int c = cg * 16 + k;
                s[c][pq] = src[(size_t)c * N + pb + pq];
            }
        }
        __syncthreads();
        float* dst = g_lat_t + (size_t)b * N * C;
        {
            int cl = tid & 63, pg = tid >> 6;
            #pragma unroll
            for (int k = 0; k < 16; k++) {
                int p = pg * 16 + k;
                dst[(size_t)(pb + p) * C + cl] = s[cl][p];
            }
        }
        return;
    }

    // ---- prep path ----
    int j = blockIdx.x - 1024;
    if (tid >= 64) return;
    int t = tid;
    float* Wf = (float*)g_Wd;
    float* red = &s[0][0];

    if (j < 64) {
        float sum = 0.f;
        #pragma unroll 8
        for (int tt = 0; tt < 64; tt++)
            sum += w_q[t * 64 + tt] * w_kv[j * 128 + tt];
        float m = 0.125f * lnq_s[t] * lnc_s[j] * sum;
        int base = ((t >> 1) * 128 + j) * 4 + (t & 1) * 2;
        Wf[base] = m; Wf[base + 1] = m;

        float bq = 0.f;
        #pragma unroll 8
        for (int c = 0; c < 64; c++) bq += lnq_b[c] * w_q[c * 64 + t];
        red[t] = w_kv[j * 128 + t] * bq;
        __syncthreads();
        if (t < 32) {
            float v = red[t] + red[t + 32];
            #pragma unroll
            for (int o = 16; o > 0; o >>= 1) v += __shfl_xor_sync(~0u, v, o);
            if (t == 0) g_bias[j] = 0.125f * lnc_s[j] * v;
        }
    } else {
        int jj = j - 64;
        float sum = 0.f;
        #pragma unroll 8
        for (int tt = 0; tt < 64; tt++)
            sum += w_kv[t * 128 + 64 + tt] * w_out[tt * 64 + jj];
        float m = lnc_s[t] * sum;
        int base = ((t >> 1) * 128 + j) * 4 + (t & 1) * 2;
        Wf[base] = m; Wf[base + 1] = m;

        float bv = 0.f;
        #pragma unroll 8
        for (int c = 0; c < 64; c++) bv += lnc_b[c] * w_kv[c * 128 + 64 + t];
        red[t] = bv * w_out[t * 64 + jj];
        __syncthreads();
        if (t < 32) {
            float v = red[t] + red[t + 32];
            #pragma unroll
            for (int o = 16; o > 0; o >>= 1) v += __shfl_xor_sync(~0u, v, o);
            if (t == 0) {
                g_bo[jj] = v + b_out[jj];
                g_bias[j] = 0.f;
            }
        }
    }
}

// ---------------------------------------------------------------------------
// K1: bilinear sample of latents. HALF-warp per point (2 points per warp).
// ---------------------------------------------------------------------------
__global__ void k_sample_lat(const float* __restrict__ coords) {
    int warp_g = (blockIdx.x * blockDim.x + threadIdx.x) >> 5;
    int lane = threadIdx.x & 31;
    int g = warp_g * 2 + (lane >> 4);
    if (g >= Bsz * N) return;
    int b = g >> 14;
    int l16 = lane & 15;

    float y = coords[(size_t)g * 2 + 0];   // xy = flip(coords)
    float x = coords[(size_t)g * 2 + 1];
    float ix = ((x + 1.f) * (float)W - 1.f) * 0.5f;
    float iy = ((y + 1.f) * (float)H - 1.f) * 0.5f;
    float x0f = floorf(ix), y0f = floorf(iy);
    float wx1 = ix - x0f, wy1 = iy - y0f;
    int x0 = (int)x0f, y0 = (int)y0f;

    const float* base = g_lat_t + (size_t)b * N * C;
    float4 acc = make_float4(0.f, 0.f, 0.f, 0.f);
    #pragma unroll
    for (int dy = 0; dy < 2; dy++) {
        #pragma unroll
        for (int dx = 0; dx < 2; dx++) {
            int xc = x0 + dx, yc = y0 + dy;
            float wgt = (dx ? wx1 : 1.f - wx1) * (dy ? wy1 : 1.f - wy1);
            bool valid = (xc >= 0) && (xc < W) && (yc >= 0) && (yc < H);
            int xi = min(max(xc, 0), W - 1);
            int yi = min(max(yc, 0), H - 1);
            float wv = valid ? wgt : 0.f;
            float4 t = ((const float4*)(base + ((size_t)yi * W + xi) * C))[l16];
            acc.x += wv * t.x;
            acc.y += wv * t.y;
            acc.z += wv * t.z;
            acc.w += wv * t.w;
        }
    }
    ((float4*)(g_qf + (size_t)g * C))[l16] = acc;
}

// ---------------------------------------------------------------------------
// K2: zq|vo GEMM + yc passthrough. EXACT R13 configuration (best measured).
// ---------------------------------------------------------------------------
__global__ void __launch_bounds__(128) k_zyv() {
    __shared__ float yq[64 * YP2];
    __shared__ float yc[64 * YP2];
    int b  = blockIdx.x >> 9;           // 512 blocks per batch
    int pb = (blockIdx.x & 511) * 32;
    int tid = threadIdx.x;

    // yq tile: global rows [p][c] -> smem [c][p], float4 reads
    const float4* qrow4 = (const float4*)(g_qf + ((size_t)b * N + pb) * 64);
    for (int idx = tid; idx < 512; idx += 128) {
        int p = idx >> 4, c4 = idx & 15;
        float4 v = qrow4[idx];
        yq[(c4 * 4 + 0) * YP2 + p] = v.x;
        yq[(c4 * 4 + 1) * YP2 + p] = v.y;
        yq[(c4 * 4 + 2) * YP2 + p] = v.z;
        yq[(c4 * 4 + 3) * YP2 + p] = v.w;
    }
    // yc tile: flat columns, already [c][p], float4 reads+writes
    const float* qb = g_qf + (size_t)b * N * 64;
    for (int idx = tid; idx < 512; idx += 128) {
        int c = idx >> 3, p4 = idx & 7;
        float4 v = *(const float4*)(qb + (size_t)c * N + pb + p4 * 4);
        *(float4*)&yc[c * YP2 + p4 * 4] = v;
    }
    __syncthreads();

    // LN (normalize only; all scales/biases folded into weights)
    if (tid < 64) {
        float* col = ((tid < 32) ? yq : yc) + (tid & 31);
        float s = 0.f, sq = 0.f;
        #pragma unroll 8
        for (int c = 0; c < 64; c++) { float v = col[c * YP2]; s += v; sq += v * v; }
        float mu = s * (1.f / 64.f);
        float var = sq * (1.f / 64.f) - mu * mu;
        float rstd = rsqrtf(var + 1e-5f);
        #pragma unroll 8
        for (int c = 0; c < 64; c++) col[c * YP2] = (col[c * YP2] - mu) * rstd;
    }
    __syncthreads();

    int warp = tid >> 5, lane = tid & 31;
    bool isQ = warp < 2;
    int p0 = (warp & 1) * 16;
    const float* yb = isQ ? yq : yc;
    int jA = (isQ ? 0 : 64) + lane;     // GEMM col
    int jB = jA + 32;

    unsigned long long accA[8], accB[8];
    {
        unsigned long long bA = dup_f32(g_bias[jA]);
        unsigned long long bB = dup_f32(g_bias[jB]);
        #pragma unroll
        for (int i = 0; i < 8; i++) { accA[i] = bA; accB[i] = bB; }
    }

    #pragma unroll 4
    for (int c2 = 0; c2 < 32; c2++) {
        ulonglong2 wA = g_Wd[c2 * 128 + jA];
        ulonglong2 wB = g_Wd[c2 * 128 + jB];
        const ulonglong2* y0 = (const ulonglong2*)&yb[(2 * c2) * YP2 + p0];
        const ulonglong2* y1 = (const ulonglong2*)&yb[(2 * c2 + 1) * YP2 + p0];
        #pragma unroll
        for (int m = 0; m < 4; m++) {
            ulonglong2 u = y0[m];
            ffma2(accA[2 * m],     u.x, wA.x);
            ffma2(accA[2 * m + 1], u.y, wA.x);
            ffma2(accB[2 * m],     u.x, wB.x);
            ffma2(accB[2 * m + 1], u.y, wB.x);
        }
        #pragma unroll
        for (int m = 0; m < 4; m++) {
            ulonglong2 u = y1[m];
            ffma2(accA[2 * m],     u.x, wA.y);
            ffma2(accA[2 * m + 1], u.y, wA.y);
            ffma2(accB[2 * m],     u.x, wB.y);
            ffma2(accB[2 * m + 1], u.y, wB.y);
        }
    }

    // store: zq -> [0:64], vo -> [128:192]
    int sA = isQ ? jA : jA + 64;
    int sB = sA + 32;
    float* ob = g_zyv + ((size_t)b * N + pb + p0) * 192;
    #pragma unroll
    for (int i = 0; i < 8; i++) {
        float2 a = ull_to_f2(accA[i]);
        float2 bv = ull_to_f2(accB[i]);
        ob[(size_t)(2 * i) * 192 + sA]     = a.x;
        ob[(size_t)(2 * i + 1) * 192 + sA] = a.y;
        ob[(size_t)(2 * i) * 192 + sB]     = bv.x;
        ob[(size_t)(2 * i + 1) * 192 + sB] = bv.y;
    }

    // yc passthrough -> [64:128] (smem unchanged since LN sync)
    for (int idx = tid; idx < 2048; idx += 128) {
        int p = idx >> 6, c = idx & 63;
        g_zyv[((size_t)b * N + pb + p) * 192 + 64 + c] = yc[c * YP2 + p];
    }
}

// ---------------------------------------------------------------------------
// K3: attention (2D-tiled, smem halo) + fused tail.
//   Sim/V phases: R10/R13 config (measured best).
//   Tail: compute per-lane (warp 0) -> smem staging -> cooperative coalesced
//   stores (cuts ~800 scattered line-touches/block to ~60). __sinf/__cosf.
// ---------------------------------------------------------------------------
__global__ void __launch_bounds__(256) k_attn(const float* __restrict__ coords,
                                              const float* __restrict__ image,
                                              float* __restrict__ out) {
    __shared__ float kv[60 * 128];   // 30720 B: per halo row: yc[0:64] | vo[64:128]
    __shared__ float st[32][26];     // tail staging: 32 queries x 25 outputs (pad 26)
    int tile = blockIdx.x;           // 2048
    int b = tile >> 9;
    int t = tile & 511;
    int th = t >> 4;
    int tw = t & 15;
    int h0 = th * 4, w0 = tw * 8;
    int tid = threadIdx.x;

    const float* kvb = g_zyv + (size_t)b * N * 192;
    for (int i = tid; i < 1920; i += 256) {
        int r = i >> 5, q4 = i & 31;
        int ri = r / 10, rj = r % 10;
        int gh = min(max(h0 - 1 + ri, 0), H - 1);
        int gw = min(max(w0 - 1 + rj, 0), W - 1);
        ((float4*)kv)[r * 32 + q4] =
            *(const float4*)(kvb + (size_t)(gh * W + gw) * 192 + 64 + q4 * 4);
    }
    __syncthreads();

    int warp = tid >> 5, lane = tid & 31;
    int g8 = lane >> 3;          // query group within warp (0..3)
    int l8 = lane & 7;           // lane within group

    // my group's query
    int qidx = warp * 4 + g8;    // 0..31 within tile
    int qh = h0 + (qidx >> 3), qw = w0 + (qidx & 7);
    int gq = b * N + qh * W + qw;

    // zq channels owned by this lane: [l8*8, l8*8+8)
    const float* zrow = g_zyv + (size_t)gq * 192 + l8 * 8;
    float4 qa = *(const float4*)(zrow);
    float4 qb4 = *(const float4*)(zrow + 4);

    // 9 neighbor rows + grouped dot products
    int rr[9];
    float att[9];
    #pragma unroll
    for (int k = 0; k < 9; k++) {
        int di = k / 3 - 1, dj = k % 3 - 1;
        int nh = min(max(qh + di, 0), H - 1) - h0 + 1;
        int nw = min(max(qw + dj, 0), W - 1) - w0 + 1;
        rr[k] = nh * 10 + nw;
        const float* kr = kv + rr[k] * 128 + l8 * 8;
        float4 ka = *(const float4*)(kr);
        float4 kb = *(const float4*)(kr + 4);
        float part = qa.x * ka.x + qa.y * ka.y + qa.z * ka.z + qa.w * ka.w
                   + qb4.x * kb.x + qb4.y * kb.y + qb4.z * kb.z + qb4.w * kb.w;
        part += __shfl_xor_sync(~0u, part, 1);
        part += __shfl_xor_sync(~0u, part, 2);
        part += __shfl_xor_sync(~0u, part, 4);
        att[k] = part;
    }
    // softmax (redundant within group)
    float m = att[0];
    #pragma unroll
    for (int k = 1; k < 9; k++) m = fmaxf(m, att[k]);
    float den = 0.f;
    #pragma unroll
    for (int k = 0; k < 9; k++) { att[k] = __expf(att[k] - m); den += att[k]; }
    float inv = 1.f / den;

    // V phase: warp-wide per query, coalesced loads/stores
    float bo0 = g_bo[lane], bo1 = g_bo[lane + 32];
    #pragma unroll
    for (int q = 0; q < 4; q++) {
        int src = q * 8;
        float o0 = 0.f, o1 = 0.f;
        #pragma unroll
        for (int k = 0; k < 9; k++) {
            float a = __shfl_sync(~0u, att[k], src);
            int r   = __shfl_sync(~0u, rr[k],  src);
            const float* vr = kv + r * 128 + 64;
            o0 += a * vr[lane];
            o1 += a * vr[32 + lane];
        }
        float ai = __shfl_sync(~0u, inv, src);
        int qi2 = warp * 4 + q;
        int g2 = b * N + (h0 + (qi2 >> 3)) * W + (w0 + (qi2 & 7));
        out[(size_t)g2 * OC + lane]      = o0 * ai + bo0;
        out[(size_t)g2 * OC + 32 + lane] = o1 * ai + bo1;
    }

    // ---- fused tail: warp 0 computes one query per lane -> smem staging ----
    if (tid < 32) {
        int tqi = tid >> 3, tqj = tid & 7;
        int g = b * N + (h0 + tqi) * W + (w0 + tqj);
        float y = coords[(size_t)g * 2 + 0];
        float x = coords[(size_t)g * 2 + 1];

        float ix = ((x + 1.f) * 256.f - 1.f) * 0.5f;
        float iy = ((y + 1.f) * 256.f - 1.f) * 0.5f;
        float x0f = floorf(ix), y0f = floorf(iy);
        float wx = ix - x0f, wy = iy - y0f;
        int x0 = (int)x0f, y0 = (int)y0f;
        const float* img = image + (size_t)b * 256 * 256;

        float ix2 = ((x + 1.f) * 128.f - 1.f) * 0.5f;
        float iy2 = ((y + 1.f) * 128.f - 1.f) * 0.5f;
        float x0f2 = floorf(ix2), y0f2 = floorf(iy2);
        float wx2 = ix2 - x0f2, wy2 = iy2 - y0f2;
        int x02 = (int)x0f2, y02 = (int)y0f2;

        float qin = 0.f, qcy = 0.f, qcx = 0.f;
        #pragma unroll
        for (int dy = 0; dy < 2; dy++) {
            #pragma unroll
            for (int dx = 0; dx < 2; dx++) {
                {
                    int xc = x0 + dx, yc2 = y0 + dy;
                    float wgt = (dx ? wx : 1.f - wx) * (dy ? wy : 1.f - wy);
                    bool valid = (xc >= 0) && (xc < 256) && (yc2 >= 0) && (yc2 < 256);
                    int xi = min(max(xc, 0), 255), yi = min(max(yc2, 0), 255);
                    qin += (valid ? wgt : 0.f) * img[yi * 256 + xi];
                }
                {
                    int xc = x02 + dx, yc2 = y02 + dy;
                    float wgt = (dx ? wx2 : 1.f - wx2) * (dy ? wy2 : 1.f - wy2);
                    bool valid = (xc >= 0) && (xc < 128) && (yc2 >= 0) && (yc2 < 128);
                    int xi = min(max(xc, 0), 127), yi = min(max(yc2, 0), 127);
                    float wv = valid ? wgt : 0.f;
                    qcy += wv * (-1.f + (2.f * yi + 1.f) * (1.f / 128.f));
                    qcx += wv * (-1.f + (2.f * xi + 1.f) * (1.f / 128.f));
                }
            }
        }

        st[tid][0] = qin;
        float cy = (qcy + 1.f) * 0.5f;
        float cx = (qcx + 1.f) * 0.5f;
        const float PI = 3.14159265358979323846f;
        #pragma unroll
        for (int k = 0; k < 6; k++) {
            float f = (float)(1 << k) * PI;
            float ay = cy * f, ax = cx * f;
            st[tid][1 + k]          = __sinf(ay);
            st[tid][1 + 6 + k]      = __sinf(ax);
            st[tid][1 + 12 + k]     = __cosf(ay);
            st[tid][1 + 12 + 6 + k] = __cosf(ax);
        }
    }
    __syncthreads();

    // cooperative coalesced store of tail outputs: 32 queries x 25 floats
    for (int idx = tid; idx < 800; idx += 256) {
        int q = idx / 25, j = idx - q * 25;
        int g = b * N + (h0 + (q >> 3)) * W + (w0 + (q & 7));
        out[(size_t)g * OC + 64 + j] = st[q][j];
    }
}

extern "C" void kernel_launch(void* const* d_in, const int* in_sizes, int n_in,
                              void* d_out, int out_size) {
    const float* image   = (const float*)d_in[0];
    const float* latents = (const float*)d_in[1];
    const float* coords  = (const float*)d_in[2];
    const float* lnq_s   = (const float*)d_in[3];
    const float* lnq_b   = (const float*)d_in[4];
    const float* lnc_s   = (const float*)d_in[5];
    const float* lnc_b   = (const float*)d_in[6];
    const float* w_q     = (const float*)d_in[7];
    const float* w_kv    = (const float*)d_in[8];
    const float* w_out   = (const float*)d_in[9];
    const float* b_out   = (const float*)d_in[10];
    float* out = (float*)d_out;

    k_pre       <<<1152, 256>>>(latents, w_q, w_kv, w_out,
                                lnq_s, lnq_b, lnc_s, lnc_b, b_out);
    k_sample_lat<<<4096, 256>>>(coords);
    k_zyv       <<<2048, 128>>>();
    k_attn      <<<2048, 256>>>(coords, image, out);
}

// round 17
// speedup vs baseline: 1.1987x; 1.0968x over previous
#include <cuda_runtime.h>
#include <cuda_fp16.h>
#include <math.h>

#define Bsz 4
#define C 64
#define H 128
#define W 128
#define N 16384   // H*W per batch
#define OC 89
#define YP2 36    // [c][p] tile pitch for 32 positions

// scratch (__device__ globals; allocation is forbidden)
__device__ float g_lat_t[Bsz * N * C];    // latents channels-last [b][p][c]
__device__ float g_qf[Bsz * N * C];       // bilinear-sampled features [b][n][c]
// per row (128 floats = 512B): zq fp32 [0:64] | yc half x64 [64:96] | vo half x64 [96:128]
__device__ float g_zyv[Bsz * N * 128];
// pre-duplicated folded weights: g_Wd[c2*128+j] = {w(2c2,j),w(2c2,j),w(2c2+1,j),w(2c2+1,j)}
__device__ ulonglong2 g_Wd[32 * 128];
__device__ float g_bias[128];             // GEMM bias: zq cols = w3, vo cols = 0
__device__ float g_bo[64];                // final output bias (beta_v@w_out + b_out)

// ---------------- f32x2 helpers (sm_103a packed fp32) ----------------------
__device__ __forceinline__ void ffma2(unsigned long long& d,
                                      unsigned long long a,
                                      unsigned long long b) {
    asm("fma.rn.f32x2 %0, %1, %2, %0;" : "+l"(d) : "l"(a), "l"(b));
}
__device__ __forceinline__ unsigned long long dup_f32(float v) {
    unsigned long long r;
    asm("mov.b64 %0, {%1, %1};" : "=l"(r) : "f"(v));
    return r;
}
__device__ __forceinline__ float2 ull_to_f2(unsigned long long v) {
    float2 r;
    asm("mov.b64 {%0, %1}, %2;" : "=f"(r.x), "=f"(r.y) : "l"(v));
    return r;
}

// ---------------------------------------------------------------------------
// K0: fused transpose + weight-prep.
// ---------------------------------------------------------------------------
__global__ void k_pre(const float* __restrict__ lat,
                      const float* __restrict__ w_q,
                      const float* __restrict__ w_kv,
                      const float* __restrict__ w_out,
                      const float* __restrict__ lnq_s,
                      const float* __restrict__ lnq_b,
                      const float* __restrict__ lnc_s,
                      const float* __restrict__ lnc_b,
                      const float* __restrict__ b_out) {
    __shared__ float s[64][65];
    int tid = threadIdx.x;
    if (blockIdx.x < 1024) {
        int b  = blockIdx.x >> 8;
        int pb = (blockIdx.x & 255) * 64;
        const float* src = lat + (size_t)b * N * C;
        {
            int pq = tid & 63, cg = tid >> 6;
            #pragma unroll
            for (int k = 0; k < 16; k++) {
                int c = cg * 16 + k;
                s[c][pq] = src[(size_t)c * N + pb + pq];
            }
        }
        __syncthreads();
        float* dst = g_lat_t + (size_t)b * N * C;
        {
            int cl = tid & 63, pg = tid >> 6;
            #pragma unroll
            for (int k = 0; k < 16; k++) {
                int p = pg * 16 + k;
                dst[(size_t)(pb + p) * C + cl] = s[cl][p];
            }
        }
        return;
    }

    // ---- prep path ----
    int j = blockIdx.x - 1024;
    if (tid >= 64) return;
    int t = tid;
    float* Wf = (float*)g_Wd;
    float* red = &s[0][0];

    if (j < 64) {
        float sum = 0.f;
        #pragma unroll 8
        for (int tt = 0; tt < 64; tt++)
            sum += w_q[t * 64 + tt] * w_kv[j * 128 + tt];
        float m = 0.125f * lnq_s[t] * lnc_s[j] * sum;
        int base = ((t >> 1) * 128 + j) * 4 + (t & 1) * 2;
        Wf[base] = m; Wf[base + 1] = m;

        float bq = 0.f;
        #pragma unroll 8
        for (int c = 0; c < 64; c++) bq += lnq_b[c] * w_q[c * 64 + t];
        red[t] = w_kv[j * 128 + t] * bq;
        __syncthreads();
        if (t < 32) {
            float v = red[t] + red[t + 32];
            #pragma unroll
            for (int o = 16; o > 0; o >>= 1) v += __shfl_xor_sync(~0u, v, o);
            if (t == 0) g_bias[j] = 0.125f * lnc_s[j] * v;
        }
    } else {
        int jj = j - 64;
        float sum = 0.f;
        #pragma unroll 8
        for (int tt = 0; tt < 64; tt++)
            sum += w_kv[t * 128 + 64 + tt] * w_out[tt * 64 + jj];
        float m = lnc_s[t] * sum;
        int base = ((t >> 1) * 128 + j) * 4 + (t & 1) * 2;
        Wf[base] = m; Wf[base + 1] = m;

        float bv = 0.f;
        #pragma unroll 8
        for (int c = 0; c < 64; c++) bv += lnc_b[c] * w_kv[c * 128 + 64 + t];
        red[t] = bv * w_out[t * 64 + jj];
        __syncthreads();
        if (t < 32) {
            float v = red[t] + red[t + 32];
            #pragma unroll
            for (int o = 16; o > 0; o >>= 1) v += __shfl_xor_sync(~0u, v, o);
            if (t == 0) {
                g_bo[jj] = v + b_out[jj];
                g_bias[j] = 0.f;
            }
        }
    }
}

// ---------------------------------------------------------------------------
// K1: bilinear sample of latents. HALF-warp per point (2 points per warp).
// ---------------------------------------------------------------------------
__global__ void k_sample_lat(const float* __restrict__ coords) {
    int warp_g = (blockIdx.x * blockDim.x + threadIdx.x) >> 5;
    int lane = threadIdx.x & 31;
    int g = warp_g * 2 + (lane >> 4);
    if (g >= Bsz * N) return;
    int b = g >> 14;
    int l16 = lane & 15;

    float y = coords[(size_t)g * 2 + 0];   // xy = flip(coords)
    float x = coords[(size_t)g * 2 + 1];
    float ix = ((x + 1.f) * (float)W - 1.f) * 0.5f;
    float iy = ((y + 1.f) * (float)H - 1.f) * 0.5f;
    float x0f = floorf(ix), y0f = floorf(iy);
    float wx1 = ix - x0f, wy1 = iy - y0f;
    int x0 = (int)x0f, y0 = (int)y0f;

    const float* base = g_lat_t + (size_t)b * N * C;
    float4 acc = make_float4(0.f, 0.f, 0.f, 0.f);
    #pragma unroll
    for (int dy = 0; dy < 2; dy++) {
        #pragma unroll
        for (int dx = 0; dx < 2; dx++) {
            int xc = x0 + dx, yc = y0 + dy;
            float wgt = (dx ? wx1 : 1.f - wx1) * (dy ? wy1 : 1.f - wy1);
            bool valid = (xc >= 0) && (xc < W) && (yc >= 0) && (yc < H);
            int xi = min(max(xc, 0), W - 1);
            int yi = min(max(yc, 0), H - 1);
            float wv = valid ? wgt : 0.f;
            float4 t = ((const float4*)(base + ((size_t)yi * W + xi) * C))[l16];
            acc.x += wv * t.x;
            acc.y += wv * t.y;
            acc.z += wv * t.z;
            acc.w += wv * t.w;
        }
    }
    ((float4*)(g_qf + (size_t)g * C))[l16] = acc;
}

// ---------------------------------------------------------------------------
// K2: zq|vo GEMM + yc passthrough. R13 GEMM core; epilogue stores yc/vo fp16.
// ---------------------------------------------------------------------------
__global__ void __launch_bounds__(128) k_zyv() {
    __shared__ float yq[64 * YP2];
    __shared__ float yc[64 * YP2];
    int b  = blockIdx.x >> 9;           // 512 blocks per batch
    int pb = (blockIdx.x & 511) * 32;
    int tid = threadIdx.x;

    // yq tile: global rows [p][c] -> smem [c][p], float4 reads
    const float4* qrow4 = (const float4*)(g_qf + ((size_t)b * N + pb) * 64);
    for (int idx = tid; idx < 512; idx += 128) {
        int p = idx >> 4, c4 = idx & 15;
        float4 v = qrow4[idx];
        yq[(c4 * 4 + 0) * YP2 + p] = v.x;
        yq[(c4 * 4 + 1) * YP2 + p] = v.y;
        yq[(c4 * 4 + 2) * YP2 + p] = v.z;
        yq[(c4 * 4 + 3) * YP2 + p] = v.w;
    }
    // yc tile: flat columns, already [c][p], float4 reads+writes
    const float* qb = g_qf + (size_t)b * N * 64;
    for (int idx = tid; idx < 512; idx += 128) {
        int c = idx >> 3, p4 = idx & 7;
        float4 v = *(const float4*)(qb + (size_t)c * N + pb + p4 * 4);
        *(float4*)&yc[c * YP2 + p4 * 4] = v;
    }
    __syncthreads();

    // LN (normalize only; all scales/biases folded into weights)
    if (tid < 64) {
        float* col = ((tid < 32) ? yq : yc) + (tid & 31);
        float s = 0.f, sq = 0.f;
        #pragma unroll 8
        for (int c = 0; c < 64; c++) { float v = col[c * YP2]; s += v; sq += v * v; }
        float mu = s * (1.f / 64.f);
        float var = sq * (1.f / 64.f) - mu * mu;
        float rstd = rsqrtf(var + 1e-5f);
        #pragma unroll 8
        for (int c = 0; c < 64; c++) col[c * YP2] = (col[c * YP2] - mu) * rstd;
    }
    __syncthreads();

    int warp = tid >> 5, lane = tid & 31;
    bool isQ = warp < 2;
    int p0 = (warp & 1) * 16;
    const float* yb = isQ ? yq : yc;
    int jA = (isQ ? 0 : 64) + lane;     // GEMM col
    int jB = jA + 32;

    unsigned long long accA[8], accB[8];
    {
        unsigned long long bA = dup_f32(g_bias[jA]);
        unsigned long long bB = dup_f32(g_bias[jB]);
        #pragma unroll
        for (int i = 0; i < 8; i++) { accA[i] = bA; accB[i] = bB; }
    }

    #pragma unroll 4
    for (int c2 = 0; c2 < 32; c2++) {
        ulonglong2 wA = g_Wd[c2 * 128 + jA];
        ulonglong2 wB = g_Wd[c2 * 128 + jB];
        const ulonglong2* y0 = (const ulonglong2*)&yb[(2 * c2) * YP2 + p0];
        const ulonglong2* y1 = (const ulonglong2*)&yb[(2 * c2 + 1) * YP2 + p0];
        #pragma unroll
        for (int m = 0; m < 4; m++) {
            ulonglong2 u = y0[m];
            ffma2(accA[2 * m],     u.x, wA.x);
            ffma2(accA[2 * m + 1], u.y, wA.x);
            ffma2(accB[2 * m],     u.x, wB.x);
            ffma2(accB[2 * m + 1], u.y, wB.x);
        }
        #pragma unroll
        for (int m = 0; m < 4; m++) {
            ulonglong2 u = y1[m];
            ffma2(accA[2 * m],     u.x, wA.y);
            ffma2(accA[2 * m + 1], u.y, wA.y);
            ffma2(accB[2 * m],     u.x, wB.y);
            ffma2(accB[2 * m + 1], u.y, wB.y);
        }
    }

    if (isQ) {
        // zq fp32 -> [0:64]
        float* ob = g_zyv + ((size_t)b * N + pb + p0) * 128;
        #pragma unroll
        for (int i = 0; i < 8; i++) {
            float2 a = ull_to_f2(accA[i]);
            float2 bv = ull_to_f2(accB[i]);
            ob[(size_t)(2 * i) * 128 + jA]     = a.x;
            ob[(size_t)(2 * i + 1) * 128 + jA] = a.y;
            ob[(size_t)(2 * i) * 128 + jB]     = bv.x;
            ob[(size_t)(2 * i + 1) * 128 + jB] = bv.y;
        }
    } else {
        // vo fp16 -> half idx [0:64] at float offset 96; channels lane, lane+32
        __half* hb = (__half*)(g_zyv + ((size_t)b * N + pb + p0) * 128 + 96);
        int chA = lane, chB = lane + 32;
        #pragma unroll
        for (int i = 0; i < 8; i++) {
            float2 a = ull_to_f2(accA[i]);
            float2 bv = ull_to_f2(accB[i]);
            hb[(size_t)(2 * i) * 256 + chA]     = __float2half(a.x);
            hb[(size_t)(2 * i + 1) * 256 + chA] = __float2half(a.y);
            hb[(size_t)(2 * i) * 256 + chB]     = __float2half(bv.x);
            hb[(size_t)(2 * i + 1) * 256 + chB] = __float2half(bv.y);
        }
    }

    // yc passthrough -> fp16 at float offset [64:96] (half2 per channel pair)
    for (int idx = tid; idx < 1024; idx += 128) {
        int p = idx >> 5, cp = idx & 31;
        __half2 hv = __floats2half2_rn(yc[(2 * cp) * YP2 + p],
                                       yc[(2 * cp + 1) * YP2 + p]);
        *((__half2*)(g_zyv + ((size_t)(b * N + pb + p)) * 128 + 64 + cp)) = hv;
    }
}

// ---------------------------------------------------------------------------
// K3: attention (2D-tiled, fp16 smem halo) + fused tail.
//   Halo row: yc half[64] | vo half[64] = 256B. Sim: 1 LDS.128/neighbor.
//   V: half2 per lane (channels 2lane, 2lane+1).
// ---------------------------------------------------------------------------
__global__ void __launch_bounds__(256) k_attn(const float* __restrict__ coords,
                                              const float* __restrict__ image,
                                              float* __restrict__ out) {
    __shared__ float kv[60 * 64];    // 15360 B: per halo row 64 float words (fp16 data)
    __shared__ float st[32][26];     // tail staging
    int tile = blockIdx.x;           // 2048
    int b = tile >> 9;
    int t = tile & 511;
    int th = t >> 4;
    int tw = t & 15;
    int h0 = th * 4, w0 = tw * 8;
    int tid = threadIdx.x;

    const float* kvb = g_zyv + (size_t)b * N * 128;
    for (int i = tid; i < 960; i += 256) {
        int r = i >> 4, q4 = i & 15;
        int ri = r / 10, rj = r % 10;
        int gh = min(max(h0 - 1 + ri, 0), H - 1);
        int gw = min(max(w0 - 1 + rj, 0), W - 1);
        ((uint4*)kv)[r * 16 + q4] =
            *(const uint4*)(kvb + (size_t)(gh * W + gw) * 128 + 64 + q4 * 4);
    }
    __syncthreads();

    int warp = tid >> 5, lane = tid & 31;
    int g8 = lane >> 3;          // query group within warp (0..3)
    int l8 = lane & 7;           // lane within group

    // my group's query
    int qidx = warp * 4 + g8;    // 0..31 within tile
    int qh = h0 + (qidx >> 3), qw = w0 + (qidx & 7);
    int gq = b * N + qh * W + qw;

    // zq channels owned by this lane: [l8*8, l8*8+8) (fp32)
    const float* zrow = g_zyv + (size_t)gq * 128 + l8 * 8;
    float4 qa = *(const float4*)(zrow);
    float4 qb4 = *(const float4*)(zrow + 4);

    // 9 neighbor rows + grouped dot products (yc in fp16: one LDS.128 each)
    int rr[9];
    float att[9];
    #pragma unroll
    for (int k = 0; k < 9; k++) {
        int di = k / 3 - 1, dj = k % 3 - 1;
        int nh = min(max(qh + di, 0), H - 1) - h0 + 1;
        int nw = min(max(qw + dj, 0), W - 1) - w0 + 1;
        rr[k] = nh * 10 + nw;
        uint4 kw = ((const uint4*)(kv + rr[k] * 64))[l8];
        const __half2* hh = (const __half2*)&kw;
        float2 f0 = __half22float2(hh[0]);
        float2 f1 = __half22float2(hh[1]);
        float2 f2 = __half22float2(hh[2]);
        float2 f3 = __half22float2(hh[3]);
        float part = qa.x * f0.x + qa.y * f0.y + qa.z * f1.x + qa.w * f1.y
                   + qb4.x * f2.x + qb4.y * f2.y + qb4.z * f3.x + qb4.w * f3.y;
        part += __shfl_xor_sync(~0u, part, 1);
        part += __shfl_xor_sync(~0u, part, 2);
        part += __shfl_xor_sync(~0u, part, 4);
        att[k] = part;
    }
    // softmax (redundant within group)
    float m = att[0];
    #pragma unroll
    for (int k = 1; k < 9; k++) m = fmaxf(m, att[k]);
    float den = 0.f;
    #pragma unroll
    for (int k = 0; k < 9; k++) { att[k] = __expf(att[k] - m); den += att[k]; }
    float inv = 1.f / den;

    // V phase: warp-wide per query; lane handles channels 2lane, 2lane+1 (half2)
    float2 bo = *(const float2*)(g_bo + 2 * lane);
    #pragma unroll
    for (int q = 0; q < 4; q++) {
        int src = q * 8;
        float o0 = 0.f, o1 = 0.f;
        #pragma unroll
        for (int k = 0; k < 9; k++) {
            float a = __shfl_sync(~0u, att[k], src);
            int r   = __shfl_sync(~0u, rr[k],  src);
            float2 v2 = __half22float2(*(const __half2*)(kv + r * 64 + 32 + lane));
            o0 += a * v2.x;
            o1 += a * v2.y;
        }
        float ai = __shfl_sync(~0u, inv, src);
        int qi2 = warp * 4 + q;
        int g2 = b * N + (h0 + (qi2 >> 3)) * W + (w0 + (qi2 & 7));
        out[(size_t)g2 * OC + 2 * lane]     = o0 * ai + bo.x;
        out[(size_t)g2 * OC + 2 * lane + 1] = o1 * ai + bo.y;
    }

    // ---- fused tail: warp 0 computes one query per lane -> smem staging ----
    if (tid < 32) {
        int tqi = tid >> 3, tqj = tid & 7;
        int g = b * N + (h0 + tqi) * W + (w0 + tqj);
        float y = coords[(size_t)g * 2 + 0];
        float x = coords[(size_t)g * 2 + 1];

        float ix = ((x + 1.f) * 256.f - 1.f) * 0.5f;
        float iy = ((y + 1.f) * 256.f - 1.f) * 0.5f;
        float x0f = floorf(ix), y0f = floorf(iy);
        float wx = ix - x0f, wy = iy - y0f;
        int x0 = (int)x0f, y0 = (int)y0f;
        const float* img = image + (size_t)b * 256 * 256;

        float ix2 = ((x + 1.f) * 128.f - 1.f) * 0.5f;
        float iy2 = ((y + 1.f) * 128.f - 1.f) * 0.5f;
        float x0f2 = floorf(ix2), y0f2 = floorf(iy2);
        float wx2 = ix2 - x0f2, wy2 = iy2 - y0f2;
        int x02 = (int)x0f2, y02 = (int)y0f2;

        float qin = 0.f, qcy = 0.f, qcx = 0.f;
        #pragma unroll
        for (int dy = 0; dy < 2; dy++) {
            #pragma unroll
            for (int dx = 0; dx < 2; dx++) {
                {
                    int xc = x0 + dx, yc2 = y0 + dy;
                    float wgt = (dx ? wx : 1.f - wx) * (dy ? wy : 1.f - wy);
                    bool valid = (xc >= 0) && (xc < 256) && (yc2 >= 0) && (yc2 < 256);
                    int xi = min(max(xc, 0), 255), yi = min(max(yc2, 0), 255);
                    qin += (valid ? wgt : 0.f) * img[yi * 256 + xi];
                }
                {
                    int xc = x02 + dx, yc2 = y02 + dy;
                    float wgt = (dx ? wx2 : 1.f - wx2) * (dy ? wy2 : 1.f - wy2);
                    bool valid = (xc >= 0) && (xc < 128) && (yc2 >= 0) && (yc2 < 128);
                    int xi = min(max(xc, 0), 127), yi = min(max(yc2, 0), 127);
                    float wv = valid ? wgt : 0.f;
                    qcy += wv * (-1.f + (2.f * yi + 1.f) * (1.f / 128.f));
                    qcx += wv * (-1.f + (2.f * xi + 1.f) * (1.f / 128.f));
                }
            }
        }

        st[tid][0] = qin;
        float cy = (qcy + 1.f) * 0.5f;
        float cx = (qcx + 1.f) * 0.5f;
        const float PI = 3.14159265358979323846f;
        #pragma unroll
        for (int k = 0; k < 6; k++) {
            float f = (float)(1 << k) * PI;
            float ay = cy * f, ax = cx * f;
            st[tid][1 + k]          = __sinf(ay);
            st[tid][1 + 6 + k]      = __sinf(ax);
            st[tid][1 + 12 + k]     = __cosf(ay);
            st[tid][1 + 12 + 6 + k] = __cosf(ax);
        }
    }
    __syncthreads();

    // cooperative coalesced store of tail outputs (padded loop: no int div)
    for (int idx = tid; idx < 1024; idx += 256) {
        int q = idx >> 5, j = idx & 31;
        if (j < 25) {
            int g = b * N + (h0 + (q >> 3)) * W + (w0 + (q & 7));
            out[(size_t)g * OC + 64 + j] = st[q][j];
        }
    }
}

extern "C" void kernel_launch(void* const* d_in, const int* in_sizes, int n_in,
                              void* d_out, int out_size) {
    const float* image   = (const float*)d_in[0];
    const float* latents = (const float*)d_in[1];
    const float* coords  = (const float*)d_in[2];
    const float* lnq_s   = (const float*)d_in[3];
    const float* lnq_b   = (const float*)d_in[4];
    const float* lnc_s   = (const float*)d_in[5];
    const float* lnc_b   = (const float*)d_in[6];
    const float* w_q     = (const float*)d_in[7];
    const float* w_kv    = (const float*)d_in[8];
    const float* w_out   = (const float*)d_in[9];
    const float* b_out   = (const float*)d_in[10];
    float* out = (float*)d_out;

    k_pre       <<<1152, 256>>>(latents, w_q, w_kv, w_out,
                                lnq_s, lnq_b, lnc_s, lnc_b, b_out);
    k_sample_lat<<<4096, 256>>>(coords);
    k_zyv       <<<2048, 128>>>();
    k_attn      <<<2048, 256>>>(coords, image, out);
}